// round 2
// baseline (speedup 1.0000x reference)
#include <cuda_runtime.h>
#include <cuda_bf16.h>

// NGram gather: out[b, j, s, e] = in[b, s + j - 2, e], zero outside [0, S).
// B=8, N=5, S=2048, E=512, fp32.
// Per (b, j) the output plane is a contiguous shifted copy of the input plane:
//   out_lin[pos] = in_lin[pos + (j-2)*E]  (zero when src row out of range)
// -> float4 fully-coalesced shifted block copies, no integer division.

static constexpr int B = 8;
static constexpr int NG = 5;
static constexpr int S = 2048;
static constexpr int E = 512;
static constexpr int E4 = E / 4;               // 128 float4 per row
static constexpr int PLANE4 = S * E4;          // 262144 float4 per (b) plane

// grid: x = PLANE4 / 256 = 1024 blocks, y = B*NG = 40 planes
__global__ void __launch_bounds__(256) ngram_kernel(
    const float4* __restrict__ in, float4* __restrict__ out)
{
    const int pos = blockIdx.x * blockDim.x + threadIdx.x;  // 0..PLANE4-1
    const int bj  = blockIdx.y;                             // 0..39
    const int j   = bj % NG;   // compile-time-cheap: NG=5, but bj is uniform
    const int b   = bj / NG;   // per-block uniform -> hoisted to uniform path

    const int src = pos + (j - 2) * E4;  // shifted source position in plane b

    float4 v = make_float4(0.f, 0.f, 0.f, 0.f);
    if (src >= 0 && src < PLANE4) {
        v = __ldg(&in[(long)b * PLANE4 + src]);
    }
    out[(long)bj * PLANE4 + pos] = v;
}

extern "C" void kernel_launch(void* const* d_in, const int* in_sizes, int n_in,
                              void* d_out, int out_size) {
    const float4* in = (const float4*)d_in[0];
    float4* out = (float4*)d_out;

    dim3 grid(PLANE4 / 256, B * NG);  // (1024, 40)
    ngram_kernel<<<grid, 256>>>(in, out);
}

// round 4
// speedup vs baseline: 1.0541x; 1.0541x over previous
#include <cuda_runtime.h>
#include <cuda_bf16.h>

// NGram gather: out[b, j, s, e] = in[b, s + j - 2, e], zero outside [0, S).
// B=8, N=5, S=2048, E=512, fp32.
// Per (b, j) plane: out_lin[pos] = in_lin[pos + (j-2)*E4] (float4 units),
// zero when out of range -> shifted block copies.
// 4 float4 per thread (front-batched LDGs, MLP=4) + streaming stores
// (__stcs) to keep the 33.5MB input L2-resident across its 5x reuse.

static constexpr int B = 8;
static constexpr int NG = 5;
static constexpr int S = 2048;
static constexpr int E = 512;
static constexpr int E4 = E / 4;               // 128 float4 per row
static constexpr int PLANE4 = S * E4;          // 262144 float4 per plane
static constexpr int VEC = 4;                  // float4s per thread
static constexpr int TPB = 256;

// grid: x = PLANE4 / (TPB*VEC) = 256, y = B*NG = 40
__global__ void __launch_bounds__(TPB) ngram_kernel(
    const float4* __restrict__ in, float4* __restrict__ out)
{
    const int bj  = blockIdx.y;            // 0..39  (uniform per block)
    const int b   = bj / NG;
    const int j   = bj - b * NG;
    const int off = (j - 2) * E4;          // shift in float4 units

    const long in_base  = (long)b  * PLANE4;
    const long out_base = (long)bj * PLANE4;

    const int pos0 = blockIdx.x * (TPB * VEC) + threadIdx.x;

    // Batch all loads first (front-batched LDG.128 x4 -> high MLP),
    // then all stores.
    float4 v[VEC];
    #pragma unroll
    for (int k = 0; k < VEC; k++) {
        const int pos = pos0 + k * TPB;
        const int src = pos + off;
        v[k] = make_float4(0.f, 0.f, 0.f, 0.f);
        if (src >= 0 && src < PLANE4) {
            v[k] = __ldg(&in[in_base + src]);
        }
    }
    #pragma unroll
    for (int k = 0; k < VEC; k++) {
        const int pos = pos0 + k * TPB;
        __stcs(&out[out_base + pos], v[k]);   // streaming: evict-first in L2
    }
}

extern "C" void kernel_launch(void* const* d_in, const int* in_sizes, int n_in,
                              void* d_out, int out_size) {
    const float4* in = (const float4*)d_in[0];
    float4* out = (float4*)d_out;

    dim3 grid(PLANE4 / (TPB * VEC), B * NG);  // (256, 40)
    ngram_kernel<<<grid, TPB>>>(in, out);
}